// round 4
// baseline (speedup 1.0000x reference)
#include <cuda_runtime.h>
#include <math.h>

// Problem constants
#define NB   4
#define NS   256
#define DM   2048
#define NH   256
#define HD   8
#define TOK  (NB * NS)   // 1024 tokens

// GEMM tiling
#define BM 128
#define BN 128
#define BK 16

// Scratch (device globals: no allocation allowed)
__device__ float g_q[TOK * DM];
__device__ float g_k[TOK * DM];
__device__ float g_v[TOK * DM];
__device__ float g_att[TOK * DM];

// ---------------------------------------------------------------------------
// Register-blocked SGEMM body with register prefetch (software pipelining):
// C[M=1024, N=2048] = A[1024,2048] @ B[2048,2048] + bias
// 128x128 tile, BK=16, 256 threads, 8x8 per thread.
// ---------------------------------------------------------------------------
__device__ __forceinline__ void gemm_body(
    const float* __restrict__ A,
    const float* __restrict__ Bw,
    const float* __restrict__ bias,
    float* __restrict__ C)
{
    __shared__ float As[BK][BM];   // A stored transposed: As[k][m]
    __shared__ float Bs[BK][BN];

    const int tid = threadIdx.x;
    const int tx  = tid & 15;      // 0..15
    const int ty  = tid >> 4;      // 0..15
    const int row0 = blockIdx.y * BM;
    const int col0 = blockIdx.x * BN;

    // A tile loads: 128 rows x 16 cols = 512 float4, 2 per thread
    const int ar = tid >> 2;           // 0..63
    const int ac = (tid & 3) << 2;     // 0,4,8,12
    // B tile loads: 16 rows x 128 cols = 512 float4, 2 per thread
    const int br = tid >> 5;           // 0..7
    const int bc = (tid & 31) << 2;    // 0..124

    float acc[8][8];
    #pragma unroll
    for (int i = 0; i < 8; i++)
        #pragma unroll
        for (int j = 0; j < 8; j++) acc[i][j] = 0.0f;

    // prefetch tile 0 into registers
    float4 a_reg[2], b_reg[2];
    #pragma unroll
    for (int it = 0; it < 2; it++) {
        a_reg[it] = *(const float4*)(A + (size_t)(row0 + ar + it * 64) * DM + ac);
        b_reg[it] = *(const float4*)(Bw + (size_t)(br + it * 8) * DM + col0 + bc);
    }

    for (int k0 = 0; k0 < DM; k0 += BK) {
        // commit prefetched tile to smem
        #pragma unroll
        for (int it = 0; it < 2; it++) {
            const int r = ar + it * 64;
            As[ac + 0][r] = a_reg[it].x;
            As[ac + 1][r] = a_reg[it].y;
            As[ac + 2][r] = a_reg[it].z;
            As[ac + 3][r] = a_reg[it].w;
            *(float4*)&Bs[br + it * 8][bc] = b_reg[it];
        }
        __syncthreads();

        // prefetch next tile while computing current
        if (k0 + BK < DM) {
            const int kn = k0 + BK;
            #pragma unroll
            for (int it = 0; it < 2; it++) {
                a_reg[it] = *(const float4*)(A + (size_t)(row0 + ar + it * 64) * DM + kn + ac);
                b_reg[it] = *(const float4*)(Bw + (size_t)(kn + br + it * 8) * DM + col0 + bc);
            }
        }

        #pragma unroll
        for (int kk = 0; kk < BK; kk++) {
            float ra[8], rb[8];
            #pragma unroll
            for (int i = 0; i < 8; i++) ra[i] = As[kk][ty * 8 + i];
            #pragma unroll
            for (int j = 0; j < 8; j++) rb[j] = Bs[kk][tx * 8 + j];
            #pragma unroll
            for (int i = 0; i < 8; i++)
                #pragma unroll
                for (int j = 0; j < 8; j++)
                    acc[i][j] += ra[i] * rb[j];
        }
        __syncthreads();
    }

    // epilogue: add bias, vectorized store
    #pragma unroll
    for (int i = 0; i < 8; i++) {
        const int r = row0 + ty * 8 + i;
        #pragma unroll
        for (int j = 0; j < 8; j += 4) {
            const int c = col0 + tx * 8 + j;
            float4 o;
            o.x = acc[i][j + 0] + bias[c + 0];
            o.y = acc[i][j + 1] + bias[c + 1];
            o.z = acc[i][j + 2] + bias[c + 2];
            o.w = acc[i][j + 3] + bias[c + 3];
            *(float4*)(C + (size_t)r * DM + c) = o;
        }
    }
}

// QKV projections in one launch: blockIdx.z selects {Wq, Wk, Wv}
__global__ __launch_bounds__(256, 2)
void qkv_kernel(const float* __restrict__ x,
                const float* __restrict__ Wq, const float* __restrict__ bq,
                const float* __restrict__ Wk, const float* __restrict__ bk,
                const float* __restrict__ Wv, const float* __restrict__ bv)
{
    const int z = blockIdx.z;
    const float* W = (z == 0) ? Wq : (z == 1) ? Wk : Wv;
    const float* b = (z == 0) ? bq : (z == 1) ? bk : bv;
    float* C = (z == 0) ? g_q : (z == 1) ? g_k : g_v;
    gemm_body(x, W, b, C);
}

// Output projection: g_att @ Wo + bo -> out
__global__ __launch_bounds__(256, 2)
void oproj_kernel(const float* __restrict__ Wo, const float* __restrict__ bo,
                  float* __restrict__ out)
{
    gemm_body(g_att, Wo, bo, out);
}

// ---------------------------------------------------------------------------
// Per-token head-mixing attention with online softmax.
// One block per token (1024 blocks), 256 threads; thread h owns head h.
//   S[h,g] = (q_h . k_g) * (cos^2(phi_s)+sin^2(phi_s)) / sqrt(8)
//   out[h] = softmax_g(S[h,:]) @ V
// ---------------------------------------------------------------------------
__global__ __launch_bounds__(256)
void attn_kernel(const float* __restrict__ phase)
{
    __shared__ float4 ks[NH * 2];   // k[g][0..7] as 2x float4
    __shared__ float4 vs[NH * 2];

    const int t = blockIdx.x;        // token = b*S + s
    const int s = t & (NS - 1);      // sequence position (S = 256)
    const int h = threadIdx.x;       // head

    const float* qp = g_q + (size_t)t * DM;
    const float* kp = g_k + (size_t)t * DM;
    const float* vp = g_v + (size_t)t * DM;

    // stage K, V for this token (each thread loads its own head's 8 values)
    ks[h * 2 + 0] = *(const float4*)(kp + h * 8);
    ks[h * 2 + 1] = *(const float4*)(kp + h * 8 + 4);
    vs[h * 2 + 0] = *(const float4*)(vp + h * 8);
    vs[h * 2 + 1] = *(const float4*)(vp + h * 8 + 4);

    const float4 q0 = *(const float4*)(qp + h * 8);
    const float4 q1 = *(const float4*)(qp + h * 8 + 4);

    const float phi = phase[s];
    float sn, c;
    __sincosf(phi, &sn, &c);
    const float scale = (c * c + sn * sn) * 0.35355339059327373f;  // *1/sqrt(8)

    __syncthreads();

    float m = -1e30f, l = 0.0f;
    float o0 = 0.f, o1 = 0.f, o2 = 0.f, o3 = 0.f;
    float o4 = 0.f, o5 = 0.f, o6 = 0.f, o7 = 0.f;

    #pragma unroll 4
    for (int g = 0; g < NH; g++) {
        const float4 k0 = ks[g * 2 + 0];
        const float4 k1 = ks[g * 2 + 1];
        float sg = q0.x * k0.x + q0.y * k0.y + q0.z * k0.z + q0.w * k0.w
                 + q1.x * k1.x + q1.y * k1.y + q1.z * k1.z + q1.w * k1.w;
        sg *= scale;

        const float mn = fmaxf(m, sg);
        const float r  = __expf(m - mn);   // 0 on first iter (m = -1e30)
        const float p  = __expf(sg - mn);
        l = l * r + p;
        m = mn;

        const float4 v0 = vs[g * 2 + 0];
        const float4 v1 = vs[g * 2 + 1];
        o0 = o0 * r + p * v0.x;  o1 = o1 * r + p * v0.y;
        o2 = o2 * r + p * v0.z;  o3 = o3 * r + p * v0.w;
        o4 = o4 * r + p * v1.x;  o5 = o5 * r + p * v1.y;
        o6 = o6 * r + p * v1.z;  o7 = o7 * r + p * v1.w;
    }

    const float inv = 1.0f / l;
    float* op = g_att + (size_t)t * DM + h * 8;
    float4 w0 = make_float4(o0 * inv, o1 * inv, o2 * inv, o3 * inv);
    float4 w1 = make_float4(o4 * inv, o5 * inv, o6 * inv, o7 * inv);
    *(float4*)(op + 0) = w0;
    *(float4*)(op + 4) = w1;
}

// ---------------------------------------------------------------------------
extern "C" void kernel_launch(void* const* d_in, const int* in_sizes, int n_in,
                              void* d_out, int out_size)
{
    const float* x     = (const float*)d_in[0];
    const float* phase = (const float*)d_in[1];
    const float* Wq    = (const float*)d_in[2];
    const float* bq    = (const float*)d_in[3];
    const float* Wk    = (const float*)d_in[4];
    const float* bk    = (const float*)d_in[5];
    const float* Wv    = (const float*)d_in[6];
    const float* bv    = (const float*)d_in[7];
    const float* Wo    = (const float*)d_in[8];
    const float* bo    = (const float*)d_in[9];
    float* out = (float*)d_out;

    dim3 qkv_grid(DM / BN, TOK / BM, 3);   // 16 x 8 x 3 = 384 blocks
    qkv_kernel<<<qkv_grid, 256>>>(x, Wq, bq, Wk, bk, Wv, bv);

    attn_kernel<<<TOK, NH>>>(phase);       // 1024 blocks x 256 threads

    dim3 o_grid(DM / BN, TOK / BM, 1);     // 128 blocks
    oproj_kernel<<<o_grid, 256>>>(Wo, bo, out);
}

// round 6
// speedup vs baseline: 2.3327x; 2.3327x over previous
#include <cuda_runtime.h>
#include <cuda_bf16.h>
#include <cstdint>
#include <math.h>

// Problem constants
#define NB   4
#define NS   256
#define DM   2048
#define NH   256
#define TOK  (NB * NS)   // 1024 tokens

// ---------------------------------------------------------------------------
// Scratch (device globals: no allocation allowed)
// ---------------------------------------------------------------------------
__device__ __align__(256) float g_q[TOK * DM];
__device__ __align__(256) float g_k[TOK * DM];
__device__ __align__(256) float g_v[TOK * DM];
__device__ __align__(256) float g_att[TOK * DM];

__device__ __align__(256) __nv_bfloat16 g_x_hi[TOK * DM];
__device__ __align__(256) __nv_bfloat16 g_x_lo[TOK * DM];
__device__ __align__(256) __nv_bfloat16 g_a_hi[TOK * DM];   // att split
__device__ __align__(256) __nv_bfloat16 g_a_lo[TOK * DM];
__device__ __align__(256) __nv_bfloat16 g_wt_hi[(size_t)4 * DM * DM];  // W^T
__device__ __align__(256) __nv_bfloat16 g_wt_lo[(size_t)4 * DM * DM];

// ---------------------------------------------------------------------------
// PTX helpers (plain sm_103-safe: mma.sync / ldmatrix / cp.async only)
// ---------------------------------------------------------------------------
__device__ __forceinline__ uint32_t smem_to_u32(const void* p) {
    uint32_t a;
    asm("{ .reg .u64 t; cvta.to.shared.u64 t, %1; cvt.u32.u64 %0, t; }"
        : "=r"(a) : "l"(p));
    return a;
}

#define CP_ASYNC16(s, g) \
    asm volatile("cp.async.cg.shared.global [%0], [%1], 16;" :: "r"(s), "l"(g))
#define CP_COMMIT() asm volatile("cp.async.commit_group;" ::: "memory")
#define CP_WAIT0()  asm volatile("cp.async.wait_group 0;" ::: "memory")
#define CP_WAIT1()  asm volatile("cp.async.wait_group 1;" ::: "memory")

#define LDSM_X4(r, addr) \
    asm volatile("ldmatrix.sync.aligned.m8n8.x4.shared.b16 {%0,%1,%2,%3}, [%4];" \
        : "=r"((r)[0]), "=r"((r)[1]), "=r"((r)[2]), "=r"((r)[3]) : "r"(addr))
#define LDSM_X2(r, addr) \
    asm volatile("ldmatrix.sync.aligned.m8n8.x2.shared.b16 {%0,%1}, [%2];" \
        : "=r"((r)[0]), "=r"((r)[1]) : "r"(addr))

#define MMA16816(c, a, b) \
    asm volatile("mma.sync.aligned.m16n8k16.row.col.f32.bf16.bf16.f32 " \
        "{%0,%1,%2,%3}, {%4,%5,%6,%7}, {%8,%9}, {%0,%1,%2,%3};" \
        : "+f"((c)[0]), "+f"((c)[1]), "+f"((c)[2]), "+f"((c)[3]) \
        : "r"((a)[0]), "r"((a)[1]), "r"((a)[2]), "r"((a)[3]), \
          "r"((b)[0]), "r"((b)[1]))

#define SWZ(x) ((x) ^ (((x) >> 3) & 0x70))

// ---------------------------------------------------------------------------
// Split helpers: x = hi + lo (bf16 each), residual error ~2^-18 |x|
// ---------------------------------------------------------------------------
__device__ __forceinline__ void split_bf16(float v, __nv_bfloat16& h, __nv_bfloat16& l) {
    h = __float2bfloat16(v);
    l = __float2bfloat16(v - __bfloat162float(h));
}

// ---------------------------------------------------------------------------
// Weight transpose + split: g_wt[z][n][k] = split(W_z[k][n])
// ---------------------------------------------------------------------------
__global__ __launch_bounds__(256)
void convert_w_kernel(const float* __restrict__ W0, const float* __restrict__ W1,
                      const float* __restrict__ W2, const float* __restrict__ W3)
{
    __shared__ float t[32][33];
    const int z = blockIdx.z;
    const float* W = (z == 0) ? W0 : (z == 1) ? W1 : (z == 2) ? W2 : W3;
    const size_t base = (size_t)z * DM * DM;
    const int n0 = blockIdx.x * 32;
    const int k0 = blockIdx.y * 32;
    const int tx = threadIdx.x & 31;
    const int ty = threadIdx.x >> 5;    // 0..7

    #pragma unroll
    for (int i = 0; i < 4; i++)
        t[ty + 8 * i][tx] = W[(size_t)(k0 + ty + 8 * i) * DM + n0 + tx];
    __syncthreads();

    #pragma unroll
    for (int i = 0; i < 4; i++) {
        float v = t[tx][ty + 8 * i];  // = W[k0+tx][n0+ty+8i]
        __nv_bfloat16 h, l;
        split_bf16(v, h, l);
        const size_t o = base + (size_t)(n0 + ty + 8 * i) * DM + k0 + tx;
        g_wt_hi[o] = h;
        g_wt_lo[o] = l;
    }
}

// ---------------------------------------------------------------------------
// Elementwise split: sel==0: x -> g_x_hi/lo ; sel==1: g_att -> g_a_hi/lo
// ---------------------------------------------------------------------------
__global__ __launch_bounds__(256)
void split_kernel(const float* __restrict__ xin, int sel)
{
    const float* src = sel ? g_att : xin;
    __nv_bfloat16* hi = sel ? g_a_hi : g_x_hi;
    __nv_bfloat16* lo = sel ? g_a_lo : g_x_lo;
    const int i = (blockIdx.x * 256 + threadIdx.x) * 4;
    float4 v = *(const float4*)(src + i);
    __nv_bfloat16 h0, l0, h1, l1, h2, l2, h3, l3;
    split_bf16(v.x, h0, l0); split_bf16(v.y, h1, l1);
    split_bf16(v.z, h2, l2); split_bf16(v.w, h3, l3);
    __nv_bfloat162 hp0 = __nv_bfloat162(h0, h1), hp1 = __nv_bfloat162(h2, h3);
    __nv_bfloat162 lp0 = __nv_bfloat162(l0, l1), lp1 = __nv_bfloat162(l2, l3);
    *(uint2*)(hi + i) = make_uint2(*(uint32_t*)&hp0, *(uint32_t*)&hp1);
    *(uint2*)(lo + i) = make_uint2(*(uint32_t*)&lp0, *(uint32_t*)&lp1);
}

// ---------------------------------------------------------------------------
// Tensor-core GEMM via mma.sync (bf16 2-term split, fp32 accum):
// C[1024,2048] = A @ W^T_layout + bias
// Tile 128(M) x 128(N) x 64(K), double-buffered cp.async, 8 warps (2x4),
// warp tile 64x32, mma.m16n8k16, SW128-swizzled smem.
//   which = base_which + blockIdx.z:
//     0/1/2 -> A=x_hi/lo,  B=Wq/Wk/Wv^T, C=g_q/g_k/g_v
//     3     -> A=att_hi/lo, B=Wo^T,      C=outp
// Dynamic smem: 2 buffers x 4 tiles x 16KB = 131072 B.
// ---------------------------------------------------------------------------
#define TILE_B   16384
#define BUF_B    (4 * TILE_B)
#define GEMM_SMEM (2 * BUF_B)
#define NT       (DM / 64)       // 32 k-iterations

__global__ __launch_bounds__(256, 1)
void gemm_tc(int base_which,
             const float* __restrict__ b0, const float* __restrict__ b1,
             const float* __restrict__ b2, float* __restrict__ outp)
{
    extern __shared__ char smem[];
    const uint32_t sb = smem_to_u32(smem);
    const int tid  = threadIdx.x;
    const int lane = tid & 31;
    const int wid  = tid >> 5;
    const int wm   = (wid >> 2) * 64;   // warp row offset: 0 / 64
    const int wn   = (wid & 3) * 32;    // warp col offset: 0/32/64/96

    const int which = base_which + blockIdx.z;
    const float* bias = (blockIdx.z == 0) ? b0 : (blockIdx.z == 1) ? b1 : b2;

    const __nv_bfloat16* a_hi = (which < 3) ? g_x_hi : g_a_hi;
    const __nv_bfloat16* a_lo = (which < 3) ? g_x_lo : g_a_lo;
    const __nv_bfloat16* b_hi = g_wt_hi + (size_t)which * DM * DM;
    const __nv_bfloat16* b_lo = g_wt_lo + (size_t)which * DM * DM;
    float* C = (which == 0) ? g_q : (which == 1) ? g_k : (which == 2) ? g_v : outp;

    const int row0 = blockIdx.y * 128;
    const int col0 = blockIdx.x * 128;

    const __nv_bfloat16* srcs[4] = { a_hi, a_lo, b_hi, b_lo };

    // accumulators: 4 m-tiles x 4 n-tiles x 4 floats
    float acc[4][4][4];
    #pragma unroll
    for (int mt = 0; mt < 4; mt++)
        #pragma unroll
        for (int nt = 0; nt < 4; nt++)
            #pragma unroll
            for (int i = 0; i < 4; i++) acc[mt][nt][i] = 0.0f;

    // ---- tile loader: 4 sub-tiles, 4 x 16B chunks per thread per sub-tile
    auto load_tiles = [&](int buf, int k0) {
        const uint32_t sbuf = sb + buf * BUF_B;
        #pragma unroll
        for (int t = 0; t < 4; t++) {
            const int base_row = (t < 2) ? row0 : col0;
            const uint32_t soff = sbuf + t * TILE_B;
            #pragma unroll
            for (int i = 0; i < 4; i++) {
                const int c   = tid + 256 * i;
                const int row = c >> 3;
                const int ci  = c & 7;
                const uint32_t so = soff + SWZ(row * 128 + ci * 16);
                const void* g = srcs[t] + (size_t)(base_row + row) * DM + k0 + ci * 8;
                CP_ASYNC16(so, g);
            }
        }
    };

    load_tiles(0, 0);
    CP_COMMIT();

    // ldmatrix lane-address components (within-tile)
    const int a_r   = wm + (lane & 15);        // + mt*16
    const int a_cb  = (lane >> 4) * 16;        // second k8-half for lanes 16-31
    const int bl15  = lane & 15;
    const int b_r   = wn + (bl15 & 7);         // + nt*8
    const int b_cb  = (bl15 >> 3) * 16;

    for (int kt = 0; kt < NT; kt++) {
        const int buf = kt & 1;
        if (kt + 1 < NT) {
            load_tiles(buf ^ 1, (kt + 1) * 64);
            CP_COMMIT();
            CP_WAIT1();
        } else {
            CP_WAIT0();
        }
        __syncthreads();

        const uint32_t sbuf = sb + buf * BUF_B;
        const uint32_t baseAh = sbuf;
        const uint32_t baseAl = sbuf + TILE_B;
        const uint32_t baseBh = sbuf + 2 * TILE_B;
        const uint32_t baseBl = sbuf + 3 * TILE_B;

        #pragma unroll
        for (int ks = 0; ks < 4; ks++) {
            uint32_t ah[4][4], al[4][4], bh[4][2], bl[4][2];
            #pragma unroll
            for (int mt = 0; mt < 4; mt++) {
                const uint32_t off = SWZ((a_r + mt * 16) * 128 + ks * 32 + a_cb);
                LDSM_X4(ah[mt], baseAh + off);
                LDSM_X4(al[mt], baseAl + off);
            }
            #pragma unroll
            for (int nt = 0; nt < 4; nt++) {
                const uint32_t off = SWZ((b_r + nt * 8) * 128 + ks * 32 + b_cb);
                LDSM_X2(bh[nt], baseBh + off);
                LDSM_X2(bl[nt], baseBl + off);
            }
            #pragma unroll
            for (int mt = 0; mt < 4; mt++)
                #pragma unroll
                for (int nt = 0; nt < 4; nt++) {
                    MMA16816(acc[mt][nt], ah[mt], bh[nt]);
                    MMA16816(acc[mt][nt], ah[mt], bl[nt]);
                    MMA16816(acc[mt][nt], al[mt], bh[nt]);
                }
        }
        __syncthreads();
    }

    // epilogue: acc layout m16n8: c0,c1 -> (row=lane/4, col=(lane%4)*2+{0,1}), c2,c3 -> row+8
    #pragma unroll
    for (int mt = 0; mt < 4; mt++) {
        #pragma unroll
        for (int nt = 0; nt < 4; nt++) {
            const int m = row0 + wm + mt * 16 + (lane >> 2);
            const int n = col0 + wn + nt * 8 + (lane & 3) * 2;
            const float2 bb = *(const float2*)(bias + n);
            float2 o0 = make_float2(acc[mt][nt][0] + bb.x, acc[mt][nt][1] + bb.y);
            float2 o1 = make_float2(acc[mt][nt][2] + bb.x, acc[mt][nt][3] + bb.y);
            *(float2*)(C + (size_t)m * DM + n)       = o0;
            *(float2*)(C + (size_t)(m + 8) * DM + n) = o1;
        }
    }
}

// ---------------------------------------------------------------------------
// Per-token head-mixing attention with online softmax (unchanged).
// ---------------------------------------------------------------------------
__global__ __launch_bounds__(256)
void attn_kernel(const float* __restrict__ phase)
{
    __shared__ float4 ks[NH * 2];
    __shared__ float4 vs[NH * 2];

    const int t = blockIdx.x;
    const int s = t & (NS - 1);
    const int h = threadIdx.x;

    const float* qp = g_q + (size_t)t * DM;
    const float* kp = g_k + (size_t)t * DM;
    const float* vp = g_v + (size_t)t * DM;

    ks[h * 2 + 0] = *(const float4*)(kp + h * 8);
    ks[h * 2 + 1] = *(const float4*)(kp + h * 8 + 4);
    vs[h * 2 + 0] = *(const float4*)(vp + h * 8);
    vs[h * 2 + 1] = *(const float4*)(vp + h * 8 + 4);

    const float4 q0 = *(const float4*)(qp + h * 8);
    const float4 q1 = *(const float4*)(qp + h * 8 + 4);

    const float phi = phase[s];
    float sn, c;
    __sincosf(phi, &sn, &c);
    const float scale = (c * c + sn * sn) * 0.35355339059327373f;

    __syncthreads();

    float m = -1e30f, l = 0.0f;
    float o0 = 0.f, o1 = 0.f, o2 = 0.f, o3 = 0.f;
    float o4 = 0.f, o5 = 0.f, o6 = 0.f, o7 = 0.f;

    #pragma unroll 4
    for (int g = 0; g < NH; g++) {
        const float4 k0 = ks[g * 2 + 0];
        const float4 k1 = ks[g * 2 + 1];
        float sg = q0.x * k0.x + q0.y * k0.y + q0.z * k0.z + q0.w * k0.w
                 + q1.x * k1.x + q1.y * k1.y + q1.z * k1.z + q1.w * k1.w;
        sg *= scale;

        const float mn = fmaxf(m, sg);
        const float r  = __expf(m - mn);
        const float p  = __expf(sg - mn);
        l = l * r + p;
        m = mn;

        const float4 v0 = vs[g * 2 + 0];
        const float4 v1 = vs[g * 2 + 1];
        o0 = o0 * r + p * v0.x;  o1 = o1 * r + p * v0.y;
        o2 = o2 * r + p * v0.z;  o3 = o3 * r + p * v0.w;
        o4 = o4 * r + p * v1.x;  o5 = o5 * r + p * v1.y;
        o6 = o6 * r + p * v1.z;  o7 = o7 * r + p * v1.w;
    }

    const float inv = 1.0f / l;
    float* op = g_att + (size_t)t * DM + h * 8;
    *(float4*)(op + 0) = make_float4(o0 * inv, o1 * inv, o2 * inv, o3 * inv);
    *(float4*)(op + 4) = make_float4(o4 * inv, o5 * inv, o6 * inv, o7 * inv);
}

// ---------------------------------------------------------------------------
extern "C" void kernel_launch(void* const* d_in, const int* in_sizes, int n_in,
                              void* d_out, int out_size)
{
    const float* x     = (const float*)d_in[0];
    const float* phase = (const float*)d_in[1];
    const float* Wq    = (const float*)d_in[2];
    const float* bq    = (const float*)d_in[3];
    const float* Wk    = (const float*)d_in[4];
    const float* bk    = (const float*)d_in[5];
    const float* Wv    = (const float*)d_in[6];
    const float* bv    = (const float*)d_in[7];
    const float* Wo    = (const float*)d_in[8];
    const float* bo    = (const float*)d_in[9];
    float* out = (float*)d_out;

    cudaFuncSetAttribute(gemm_tc, cudaFuncAttributeMaxDynamicSharedMemorySize,
                         GEMM_SMEM);

    // weight transpose+split and x split
    convert_w_kernel<<<dim3(DM / 32, DM / 32, 4), 256>>>(Wq, Wk, Wv, Wo);
    split_kernel<<<(TOK * DM) / 1024, 256>>>(x, 0);

    // Q, K, V projections (tensor cores via mma.sync)
    gemm_tc<<<dim3(DM / 128, TOK / 128, 3), 256, GEMM_SMEM>>>(0, bq, bk, bv, out);

    // attention
    attn_kernel<<<TOK, NH>>>(phase);

    // att split + O projection
    split_kernel<<<(TOK * DM) / 1024, 256>>>(x, 1);
    gemm_tc<<<dim3(DM / 128, TOK / 128, 1), 256, GEMM_SMEM>>>(3, bo, bo, bo, out);
}

// round 7
// speedup vs baseline: 2.4614x; 1.0552x over previous
#include <cuda_runtime.h>
#include <cuda_bf16.h>
#include <cstdint>
#include <math.h>

// Problem constants
#define NB   4
#define NS   256
#define DM   2048
#define NH   256
#define TOK  (NB * NS)   // 1024 tokens

// ---------------------------------------------------------------------------
// Scratch (device globals: no allocation allowed)
// ---------------------------------------------------------------------------
__device__ __align__(256) float g_q[TOK * DM];
__device__ __align__(256) float g_k[TOK * DM];
__device__ __align__(256) float g_v[TOK * DM];

__device__ __align__(256) __nv_bfloat16 g_x_hi[TOK * DM];
__device__ __align__(256) __nv_bfloat16 g_x_lo[TOK * DM];
__device__ __align__(256) __nv_bfloat16 g_a_hi[TOK * DM];   // att split (written by attn)
__device__ __align__(256) __nv_bfloat16 g_a_lo[TOK * DM];
__device__ __align__(256) __nv_bfloat16 g_wt_hi[(size_t)4 * DM * DM];  // W^T
__device__ __align__(256) __nv_bfloat16 g_wt_lo[(size_t)4 * DM * DM];

// ---------------------------------------------------------------------------
// PTX helpers (plain sm_103-safe: mma.sync / ldmatrix / cp.async only)
// ---------------------------------------------------------------------------
__device__ __forceinline__ uint32_t smem_to_u32(const void* p) {
    uint32_t a;
    asm("{ .reg .u64 t; cvta.to.shared.u64 t, %1; cvt.u32.u64 %0, t; }"
        : "=r"(a) : "l"(p));
    return a;
}

#define CP_ASYNC16(s, g) \
    asm volatile("cp.async.cg.shared.global [%0], [%1], 16;" :: "r"(s), "l"(g))
#define CP_COMMIT() asm volatile("cp.async.commit_group;" ::: "memory")
#define CP_WAIT0()  asm volatile("cp.async.wait_group 0;" ::: "memory")
#define CP_WAIT1()  asm volatile("cp.async.wait_group 1;" ::: "memory")

#define LDSM_X4(r, addr) \
    asm volatile("ldmatrix.sync.aligned.m8n8.x4.shared.b16 {%0,%1,%2,%3}, [%4];" \
        : "=r"((r)[0]), "=r"((r)[1]), "=r"((r)[2]), "=r"((r)[3]) : "r"(addr))
#define LDSM_X2(r, addr) \
    asm volatile("ldmatrix.sync.aligned.m8n8.x2.shared.b16 {%0,%1}, [%2];" \
        : "=r"((r)[0]), "=r"((r)[1]) : "r"(addr))

#define MMA16816(c, a, b) \
    asm volatile("mma.sync.aligned.m16n8k16.row.col.f32.bf16.bf16.f32 " \
        "{%0,%1,%2,%3}, {%4,%5,%6,%7}, {%8,%9}, {%0,%1,%2,%3};" \
        : "+f"((c)[0]), "+f"((c)[1]), "+f"((c)[2]), "+f"((c)[3]) \
        : "r"((a)[0]), "r"((a)[1]), "r"((a)[2]), "r"((a)[3]), \
          "r"((b)[0]), "r"((b)[1]))

#define SWZ(x) ((x) ^ (((x) >> 3) & 0x70))

// ---------------------------------------------------------------------------
// Split helpers: x = hi + lo (bf16 each), residual error ~2^-18 |x|
// ---------------------------------------------------------------------------
__device__ __forceinline__ void split_bf16(float v, __nv_bfloat16& h, __nv_bfloat16& l) {
    h = __float2bfloat16(v);
    l = __float2bfloat16(v - __bfloat162float(h));
}

// ---------------------------------------------------------------------------
// Weight transpose + split: g_wt[z][n][k] = split(W_z[k][n])
// ---------------------------------------------------------------------------
__global__ __launch_bounds__(256)
void convert_w_kernel(const float* __restrict__ W0, const float* __restrict__ W1,
                      const float* __restrict__ W2, const float* __restrict__ W3)
{
    __shared__ float t[32][33];
    const int z = blockIdx.z;
    const float* W = (z == 0) ? W0 : (z == 1) ? W1 : (z == 2) ? W2 : W3;
    const size_t base = (size_t)z * DM * DM;
    const int n0 = blockIdx.x * 32;
    const int k0 = blockIdx.y * 32;
    const int tx = threadIdx.x & 31;
    const int ty = threadIdx.x >> 5;    // 0..7

    #pragma unroll
    for (int i = 0; i < 4; i++)
        t[ty + 8 * i][tx] = W[(size_t)(k0 + ty + 8 * i) * DM + n0 + tx];
    __syncthreads();

    #pragma unroll
    for (int i = 0; i < 4; i++) {
        float v = t[tx][ty + 8 * i];  // = W[k0+tx][n0+ty+8i]
        __nv_bfloat16 h, l;
        split_bf16(v, h, l);
        const size_t o = base + (size_t)(n0 + ty + 8 * i) * DM + k0 + tx;
        g_wt_hi[o] = h;
        g_wt_lo[o] = l;
    }
}

// ---------------------------------------------------------------------------
// Elementwise split of input x -> g_x_hi/lo
// ---------------------------------------------------------------------------
__global__ __launch_bounds__(256)
void split_kernel(const float* __restrict__ src)
{
    const int i = (blockIdx.x * 256 + threadIdx.x) * 4;
    float4 v = *(const float4*)(src + i);
    __nv_bfloat16 h0, l0, h1, l1, h2, l2, h3, l3;
    split_bf16(v.x, h0, l0); split_bf16(v.y, h1, l1);
    split_bf16(v.z, h2, l2); split_bf16(v.w, h3, l3);
    __nv_bfloat162 hp0 = __nv_bfloat162(h0, h1), hp1 = __nv_bfloat162(h2, h3);
    __nv_bfloat162 lp0 = __nv_bfloat162(l0, l1), lp1 = __nv_bfloat162(l2, l3);
    *(uint2*)(g_x_hi + i) = make_uint2(*(uint32_t*)&hp0, *(uint32_t*)&hp1);
    *(uint2*)(g_x_lo + i) = make_uint2(*(uint32_t*)&lp0, *(uint32_t*)&lp1);
}

// ---------------------------------------------------------------------------
// Tensor-core GEMM via mma.sync (bf16 2-term split, fp32 accum):
// Tile 128(M) x 128(N) x 64(K), 3-stage cp.async pipeline, 8 warps (2x4),
// warp tile 64x32, mma.m16n8k16, SW128-swizzled smem.
//   which = base_which + blockIdx.z:
//     0/1/2 -> A=x_hi/lo,  B=Wq/Wk/Wv^T, C=g_q/g_k/g_v
//     3     -> A=att_hi/lo, B=Wo^T,      C=outp
// Dynamic smem: 3 stages x 4 tiles x 16KB = 196608 B.
// ---------------------------------------------------------------------------
#define TILE_B   16384
#define BUF_B    (4 * TILE_B)
#define NSTAGE   3
#define GEMM_SMEM (NSTAGE * BUF_B)
#define NT       (DM / 64)       // 32 k-iterations

__global__ __launch_bounds__(256, 1)
void gemm_tc(int base_which,
             const float* __restrict__ b0, const float* __restrict__ b1,
             const float* __restrict__ b2, float* __restrict__ outp)
{
    extern __shared__ char smem[];
    const uint32_t sb = smem_to_u32(smem);
    const int tid  = threadIdx.x;
    const int lane = tid & 31;
    const int wid  = tid >> 5;
    const int wm   = (wid >> 2) * 64;   // warp row offset: 0 / 64
    const int wn   = (wid & 3) * 32;    // warp col offset: 0/32/64/96

    const int which = base_which + blockIdx.z;
    const float* bias = (blockIdx.z == 0) ? b0 : (blockIdx.z == 1) ? b1 : b2;

    const __nv_bfloat16* a_hi = (which < 3) ? g_x_hi : g_a_hi;
    const __nv_bfloat16* a_lo = (which < 3) ? g_x_lo : g_a_lo;
    const __nv_bfloat16* b_hi = g_wt_hi + (size_t)which * DM * DM;
    const __nv_bfloat16* b_lo = g_wt_lo + (size_t)which * DM * DM;
    float* C = (which == 0) ? g_q : (which == 1) ? g_k : (which == 2) ? g_v : outp;

    const int row0 = blockIdx.y * 128;
    const int col0 = blockIdx.x * 128;

    const __nv_bfloat16* srcs[4] = { a_hi, a_lo, b_hi, b_lo };

    float acc[4][4][4];
    #pragma unroll
    for (int mt = 0; mt < 4; mt++)
        #pragma unroll
        for (int nt = 0; nt < 4; nt++)
            #pragma unroll
            for (int i = 0; i < 4; i++) acc[mt][nt][i] = 0.0f;

    auto load_tiles = [&](int buf, int k0) {
        const uint32_t sbuf = sb + buf * BUF_B;
        #pragma unroll
        for (int t = 0; t < 4; t++) {
            const int base_row = (t < 2) ? row0 : col0;
            const uint32_t soff = sbuf + t * TILE_B;
            #pragma unroll
            for (int i = 0; i < 4; i++) {
                const int c   = tid + 256 * i;
                const int row = c >> 3;
                const int ci  = c & 7;
                const uint32_t so = soff + SWZ(row * 128 + ci * 16);
                const void* g = srcs[t] + (size_t)(base_row + row) * DM + k0 + ci * 8;
                CP_ASYNC16(so, g);
            }
        }
    };

    // prologue: 2 stages in flight
    load_tiles(0, 0);
    CP_COMMIT();
    load_tiles(1, 64);
    CP_COMMIT();

    const int a_r   = wm + (lane & 15);
    const int a_cb  = (lane >> 4) * 16;
    const int bl15  = lane & 15;
    const int b_r   = wn + (bl15 & 7);
    const int b_cb  = (bl15 >> 3) * 16;

    for (int kt = 0; kt < NT; kt++) {
        if (kt == NT - 1) { CP_WAIT0(); } else { CP_WAIT1(); }
        __syncthreads();   // tile kt visible to all; prior compute on buf (kt+2)%3 done

        if (kt + 2 < NT) {
            load_tiles((kt + 2) % NSTAGE, (kt + 2) * 64);
            CP_COMMIT();
        }

        const uint32_t sbuf = sb + (kt % NSTAGE) * BUF_B;
        const uint32_t baseAh = sbuf;
        const uint32_t baseAl = sbuf + TILE_B;
        const uint32_t baseBh = sbuf + 2 * TILE_B;
        const uint32_t baseBl = sbuf + 3 * TILE_B;

        #pragma unroll
        for (int ks = 0; ks < 4; ks++) {
            uint32_t ah[4][4], al[4][4], bh[4][2], bl[4][2];
            #pragma unroll
            for (int mt = 0; mt < 4; mt++) {
                const uint32_t off = SWZ((a_r + mt * 16) * 128 + ks * 32 + a_cb);
                LDSM_X4(ah[mt], baseAh + off);
                LDSM_X4(al[mt], baseAl + off);
            }
            #pragma unroll
            for (int nt = 0; nt < 4; nt++) {
                const uint32_t off = SWZ((b_r + nt * 8) * 128 + ks * 32 + b_cb);
                LDSM_X2(bh[nt], baseBh + off);
                LDSM_X2(bl[nt], baseBl + off);
            }
            #pragma unroll
            for (int mt = 0; mt < 4; mt++)
                #pragma unroll
                for (int nt = 0; nt < 4; nt++) {
                    MMA16816(acc[mt][nt], ah[mt], bh[nt]);
                    MMA16816(acc[mt][nt], ah[mt], bl[nt]);
                    MMA16816(acc[mt][nt], al[mt], bh[nt]);
                }
        }
    }

    // epilogue
    #pragma unroll
    for (int mt = 0; mt < 4; mt++) {
        #pragma unroll
        for (int nt = 0; nt < 4; nt++) {
            const int m = row0 + wm + mt * 16 + (lane >> 2);
            const int n = col0 + wn + nt * 8 + (lane & 3) * 2;
            const float2 bb = *(const float2*)(bias + n);
            float2 o0 = make_float2(acc[mt][nt][0] + bb.x, acc[mt][nt][1] + bb.y);
            float2 o1 = make_float2(acc[mt][nt][2] + bb.x, acc[mt][nt][3] + bb.y);
            *(float2*)(C + (size_t)m * DM + n)       = o0;
            *(float2*)(C + (size_t)(m + 8) * DM + n) = o1;
        }
    }
}

// ---------------------------------------------------------------------------
// Per-token head-mixing attention, UNSTABILIZED softmax (scores bounded |s|<~8,
// exp safe in fp32), fused bf16 hi/lo split of the output.
//   S[h,g] = (q_h . k_g) * (cos^2+sin^2)(phi_s) / sqrt(8); out = softmax @ V
// ---------------------------------------------------------------------------
__global__ __launch_bounds__(256)
void attn_kernel(const float* __restrict__ phase)
{
    __shared__ float4 ks[NH * 2];
    __shared__ float4 vs[NH * 2];

    const int t = blockIdx.x;
    const int s = t & (NS - 1);
    const int h = threadIdx.x;

    const float* qp = g_q + (size_t)t * DM;
    const float* kp = g_k + (size_t)t * DM;
    const float* vp = g_v + (size_t)t * DM;

    ks[h * 2 + 0] = *(const float4*)(kp + h * 8);
    ks[h * 2 + 1] = *(const float4*)(kp + h * 8 + 4);
    vs[h * 2 + 0] = *(const float4*)(vp + h * 8);
    vs[h * 2 + 1] = *(const float4*)(vp + h * 8 + 4);

    const float4 q0 = *(const float4*)(qp + h * 8);
    const float4 q1 = *(const float4*)(qp + h * 8 + 4);

    const float phi = phase[s];
    float sn, c;
    __sincosf(phi, &sn, &c);
    const float scale = (c * c + sn * sn) * 0.35355339059327373f;

    __syncthreads();

    float l = 0.0f;
    float o0 = 0.f, o1 = 0.f, o2 = 0.f, o3 = 0.f;
    float o4 = 0.f, o5 = 0.f, o6 = 0.f, o7 = 0.f;

    #pragma unroll 4
    for (int g = 0; g < NH; g++) {
        const float4 k0 = ks[g * 2 + 0];
        const float4 k1 = ks[g * 2 + 1];
        float sg = q0.x * k0.x + q0.y * k0.y + q0.z * k0.z + q0.w * k0.w
                 + q1.x * k1.x + q1.y * k1.y + q1.z * k1.z + q1.w * k1.w;
        const float p = __expf(sg * scale);
        l += p;

        const float4 v0 = vs[g * 2 + 0];
        const float4 v1 = vs[g * 2 + 1];
        o0 += p * v0.x;  o1 += p * v0.y;
        o2 += p * v0.z;  o3 += p * v0.w;
        o4 += p * v1.x;  o5 += p * v1.y;
        o6 += p * v1.z;  o7 += p * v1.w;
    }

    const float inv = 1.0f / l;
    float vals[8] = { o0 * inv, o1 * inv, o2 * inv, o3 * inv,
                      o4 * inv, o5 * inv, o6 * inv, o7 * inv };
    __nv_bfloat16 hv[8], lv[8];
    #pragma unroll
    for (int i = 0; i < 8; i++) split_bf16(vals[i], hv[i], lv[i]);

    const size_t ob = (size_t)t * DM + h * 8;
    __nv_bfloat162 hp0(hv[0], hv[1]), hp1(hv[2], hv[3]), hp2(hv[4], hv[5]), hp3(hv[6], hv[7]);
    __nv_bfloat162 lp0(lv[0], lv[1]), lp1(lv[2], lv[3]), lp2(lv[4], lv[5]), lp3(lv[6], lv[7]);
    uint4 hw = make_uint4(*(uint32_t*)&hp0, *(uint32_t*)&hp1, *(uint32_t*)&hp2, *(uint32_t*)&hp3);
    uint4 lw = make_uint4(*(uint32_t*)&lp0, *(uint32_t*)&lp1, *(uint32_t*)&lp2, *(uint32_t*)&lp3);
    *(uint4*)(g_a_hi + ob) = hw;
    *(uint4*)(g_a_lo + ob) = lw;
}

// ---------------------------------------------------------------------------
extern "C" void kernel_launch(void* const* d_in, const int* in_sizes, int n_in,
                              void* d_out, int out_size)
{
    const float* x     = (const float*)d_in[0];
    const float* phase = (const float*)d_in[1];
    const float* Wq    = (const float*)d_in[2];
    const float* bq    = (const float*)d_in[3];
    const float* Wk    = (const float*)d_in[4];
    const float* bk    = (const float*)d_in[5];
    const float* Wv    = (const float*)d_in[6];
    const float* bv    = (const float*)d_in[7];
    const float* Wo    = (const float*)d_in[8];
    const float* bo    = (const float*)d_in[9];
    float* out = (float*)d_out;

    cudaFuncSetAttribute(gemm_tc, cudaFuncAttributeMaxDynamicSharedMemorySize,
                         GEMM_SMEM);

    // weight transpose+split and x split
    convert_w_kernel<<<dim3(DM / 32, DM / 32, 4), 256>>>(Wq, Wk, Wv, Wo);
    split_kernel<<<(TOK * DM) / 1024, 256>>>(x);

    // Q, K, V projections (tensor cores via mma.sync)
    gemm_tc<<<dim3(DM / 128, TOK / 128, 3), 256, GEMM_SMEM>>>(0, bq, bk, bv, out);

    // attention (writes split output directly)
    attn_kernel<<<TOK, NH>>>(phase);

    // O projection
    gemm_tc<<<dim3(DM / 128, TOK / 128, 1), 256, GEMM_SMEM>>>(3, bo, bo, bo, out);
}